// round 2
// baseline (speedup 1.0000x reference)
#include <cuda_runtime.h>
#include <cuda_bf16.h>
#include <mma.h>

using namespace nvcuda;

// ---------------- problem constants ----------------
#define TOK    8192      // B*S tokens
#define DDIM   1024
#define HDIM   512
#define NEXP   16
#define TOPK   2
#define ROWS_TOT (TOK*TOPK)   // 16384 (each token -> exactly 2 expert rows)

// ---------------- GEMM tiling ----------------
#define BM 128
#define BN 64
#define BK 32
#define XLD (BK+8)   // 40 bf16 -> 80B rows (16B multiple)
#define WLD (BN+8)   // 72 bf16 -> 144B rows
#define SLD (BN+4)   // 68 f32  -> 272B rows

// ---------------- device scratch (static, no allocs) ----------------
__device__ alignas(256) __nv_bfloat16 g_xbf[(size_t)TOK*DDIM];            // 16 MB
__device__ alignas(256) float g_h[(size_t)(ROWS_TOT+BM)*HDIM];            // ~34 MB
__device__ alignas(256) float g_y[(size_t)(ROWS_TOT+BM)*DDIM];            // ~68 MB
__device__ int   g_counts[NEXP];
__device__ int   g_fill[NEXP];
__device__ int   g_offsets[NEXP+1];
__device__ int   g_topk_idx[TOK*TOPK];
__device__ float g_topk_w[TOK*TOPK];
__device__ int   g_tokList[ROWS_TOT];
__device__ float g_wList[ROWS_TOT];
__device__ int   g_rowOf[TOK*TOPK];

// ---------------- 1) zero per-expert counters ----------------
__global__ void k_init() {
    int i = threadIdx.x;
    if (i < NEXP) g_counts[i] = 0;
}

// ---------------- 2) fp32 router: logits, softmax-top2, bf16 cast of x ----------------
// one warp per token, 8 tokens per 256-thread block
__global__ __launch_bounds__(256) void k_router(const float* __restrict__ x,
                                                const float* __restrict__ gw) {
    int lane = threadIdx.x & 31;
    int t = blockIdx.x * 8 + (threadIdx.x >> 5);
    const float* xrow = x + (size_t)t * DDIM;

    float acc[NEXP];
#pragma unroll
    for (int e = 0; e < NEXP; e++) acc[e] = 0.f;

    for (int d = lane; d < DDIM; d += 32) {
        float xv = xrow[d];
        const float4* g4 = (const float4*)(gw + (size_t)d * NEXP);
#pragma unroll
        for (int q = 0; q < 4; q++) {
            float4 v = g4[q];
            acc[q*4+0] += xv * v.x;
            acc[q*4+1] += xv * v.y;
            acc[q*4+2] += xv * v.z;
            acc[q*4+3] += xv * v.w;
        }
    }
#pragma unroll
    for (int off = 16; off; off >>= 1)
#pragma unroll
        for (int e = 0; e < NEXP; e++)
            acc[e] += __shfl_xor_sync(0xffffffffu, acc[e], off);

    if (lane == 0) {
        int e0 = 0; float l0 = acc[0];
#pragma unroll
        for (int e = 1; e < NEXP; e++) if (acc[e] > l0) { l0 = acc[e]; e0 = e; }
        int e1 = -1; float l1 = -3.4e38f;
#pragma unroll
        for (int e = 0; e < NEXP; e++) if (e != e0 && acc[e] > l1) { l1 = acc[e]; e1 = e; }
        // renormalized top-2 softmax weights (l0 >= l1)
        float p1 = expf(l1 - l0);
        float w0 = 1.f / (1.f + p1);
        float w1 = p1 * w0;
        g_topk_idx[2*t]   = e0;  g_topk_idx[2*t+1] = e1;
        g_topk_w[2*t]     = w0;  g_topk_w[2*t+1]   = w1;
        atomicAdd(&g_counts[e0], 1);
        atomicAdd(&g_counts[e1], 1);
    }

    // cast x row to bf16 for the expert GEMMs
    const float4* xr4 = (const float4*)xrow;
    __nv_bfloat162* xb2 = (__nv_bfloat162*)(g_xbf + (size_t)t * DDIM);
    for (int i = lane; i < DDIM/4; i += 32) {
        float4 v = xr4[i];
        xb2[2*i]   = __floats2bfloat162_rn(v.x, v.y);
        xb2[2*i+1] = __floats2bfloat162_rn(v.z, v.w);
    }
}

// ---------------- 3) exclusive scan of 16 counts ----------------
__global__ void k_scan() {
    if (threadIdx.x == 0) {
        int s = 0;
        for (int e = 0; e < NEXP; e++) { g_offsets[e] = s; s += g_counts[e]; g_fill[e] = 0; }
        g_offsets[NEXP] = s;   // == ROWS_TOT
    }
}

// ---------------- 4) scatter tokens into per-expert row lists ----------------
__global__ void k_scatter() {
    int t = blockIdx.x * 256 + threadIdx.x;
    if (t >= TOK) return;
#pragma unroll
    for (int k = 0; k < TOPK; k++) {
        int e = g_topk_idx[2*t+k];
        int pos = atomicAdd(&g_fill[e], 1);
        int row = g_offsets[e] + pos;
        g_tokList[row] = t;
        g_wList[row]   = g_topk_w[2*t+k];
        g_rowOf[2*t+k] = row;
    }
}

// ---------------- 5) grouped up-GEMM: h = silu(X*W1) .* (X*W3) ----------------
// grid: (H/BN=8, TOK/BM=64, NEXP=16); block 256 (8 warps, each warp = 16 rows x 64 cols)
__global__ __launch_bounds__(256) void k_up(const float* __restrict__ w1,
                                            const float* __restrict__ w3) {
    int e = blockIdx.z;
    int n_e = g_counts[e];
    int rowBase = blockIdx.y * BM;
    if (rowBase >= n_e) return;
    int valid = min(BM, n_e - rowBase);
    int hbase = blockIdx.x * BN;
    int off = g_offsets[e];
    int tid = threadIdx.x;

    __shared__ alignas(16) unsigned char smem[BM * SLD * 4];   // 34816B, unioned
    __shared__ int toks[BM];
    __nv_bfloat16* Xs  = (__nv_bfloat16*)smem;          // [BM][XLD]
    __nv_bfloat16* W1s = Xs + BM * XLD;                 // [BK][WLD]
    __nv_bfloat16* W3s = W1s + BK * WLD;                // [BK][WLD]
    float* Hs = (float*)smem;                           // [BM][SLD] (epilogue)

    if (tid < BM) toks[tid] = (tid < valid) ? g_tokList[off + rowBase + tid] : -1;
    __syncthreads();

    int wid = tid >> 5;
    int m0 = wid * 16;

    wmma::fragment<wmma::accumulator,16,16,16,float> acc1[4], acc3[4];
#pragma unroll
    for (int j = 0; j < 4; j++) { wmma::fill_fragment(acc1[j], 0.f); wmma::fill_fragment(acc3[j], 0.f); }

    for (int ko = 0; ko < DDIM; ko += BK) {
        // X tile 128x32 bf16 (gathered rows): 512 uint4, 2 per thread
#pragma unroll
        for (int i = 0; i < 2; i++) {
            int c = tid + i * 256;
            int r = c >> 2, s = c & 3;
            uint4 v = make_uint4(0u,0u,0u,0u);
            int tk = toks[r];
            if (tk >= 0) v = *(const uint4*)(g_xbf + (size_t)tk * DDIM + ko + s * 8);
            *(uint4*)(Xs + r * XLD + s * 8) = v;
        }
        // W1/W3 tiles 32x64 fp32 -> bf16: 512 float4 each, 2 per thread
#pragma unroll
        for (int i = 0; i < 2; i++) {
            int f = tid + i * 256;
            int r = f >> 4, s = f & 15;
            size_t gi = ((size_t)(e * DDIM + ko + r)) * HDIM + hbase + s * 4;
            float4 a = *(const float4*)(w1 + gi);
            float4 b = *(const float4*)(w3 + gi);
            __nv_bfloat162* p1 = (__nv_bfloat162*)(W1s + r * WLD + s * 4);
            p1[0] = __floats2bfloat162_rn(a.x, a.y);
            p1[1] = __floats2bfloat162_rn(a.z, a.w);
            __nv_bfloat162* p3 = (__nv_bfloat162*)(W3s + r * WLD + s * 4);
            p3[0] = __floats2bfloat162_rn(b.x, b.y);
            p3[1] = __floats2bfloat162_rn(b.z, b.w);
        }
        __syncthreads();
#pragma unroll
        for (int ks = 0; ks < BK; ks += 16) {
            wmma::fragment<wmma::matrix_a,16,16,16,__nv_bfloat16,wmma::row_major> af;
            wmma::load_matrix_sync(af, Xs + m0 * XLD + ks, XLD);
#pragma unroll
            for (int j = 0; j < 4; j++) {
                wmma::fragment<wmma::matrix_b,16,16,16,__nv_bfloat16,wmma::row_major> bf;
                wmma::load_matrix_sync(bf, W1s + ks * WLD + j * 16, WLD);
                wmma::mma_sync(acc1[j], af, bf, acc1[j]);
                wmma::load_matrix_sync(bf, W3s + ks * WLD + j * 16, WLD);
                wmma::mma_sync(acc3[j], af, bf, acc3[j]);
            }
        }
        __syncthreads();
    }

    // SwiGLU combine in-register (accumulator fragments share element mapping)
#pragma unroll
    for (int j = 0; j < 4; j++)
#pragma unroll
        for (int el = 0; el < acc1[j].num_elements; el++) {
            float v1 = acc1[j].x[el];
            float sv = v1 / (1.f + __expf(-v1));
            acc1[j].x[el] = sv * acc3[j].x[el];
        }
#pragma unroll
    for (int j = 0; j < 4; j++)
        wmma::store_matrix_sync(Hs + m0 * SLD + j * 16, acc1[j], SLD, wmma::mem_row_major);
    __syncthreads();

    // guarded write to fp32 h scratch: 2048 float4, 8 per thread
#pragma unroll
    for (int i = 0; i < 8; i++) {
        int f = tid + i * 256;
        int r = f >> 4, s = f & 15;
        if (r < valid)
            *(float4*)(g_h + (size_t)(off + rowBase + r) * HDIM + hbase + s * 4) =
                *(float4*)(Hs + r * SLD + s * 4);
    }
}

// ---------------- 6) grouped down-GEMM: y_row = w_row * (h_row * W2) ----------------
// grid: (D/BN=16, TOK/BM=64, NEXP=16); block 256
__global__ __launch_bounds__(256) void k_down(const float* __restrict__ w2) {
    int e = blockIdx.z;
    int n_e = g_counts[e];
    int rowBase = blockIdx.y * BM;
    if (rowBase >= n_e) return;
    int valid = min(BM, n_e - rowBase);
    int dbase = blockIdx.x * BN;
    int off = g_offsets[e];
    int tid = threadIdx.x;

    __shared__ alignas(16) unsigned char smem[BM * SLD * 4];
    __shared__ float ws[BM];
    __nv_bfloat16* HsA = (__nv_bfloat16*)smem;          // [BM][XLD]
    __nv_bfloat16* W2s = HsA + BM * XLD;                // [BK][WLD]
    float* Cs = (float*)smem;                           // [BM][SLD]

    if (tid < BM) ws[tid] = (tid < valid) ? g_wList[off + rowBase + tid] : 0.f;
    __syncthreads();

    int wid = tid >> 5;
    int m0 = wid * 16;

    wmma::fragment<wmma::accumulator,16,16,16,float> acc[4];
#pragma unroll
    for (int j = 0; j < 4; j++) wmma::fill_fragment(acc[j], 0.f);

    for (int ko = 0; ko < HDIM; ko += BK) {
        // h tile 128x32 fp32 -> bf16 (rows contiguous per expert; padded array keeps OOB reads safe)
#pragma unroll
        for (int i = 0; i < 4; i++) {
            int f = tid + i * 256;
            int r = f >> 3, s = f & 7;
            float4 v = *(const float4*)(g_h + (size_t)(off + rowBase + r) * HDIM + ko + s * 4);
            __nv_bfloat162* p = (__nv_bfloat162*)(HsA + r * XLD + s * 4);
            p[0] = __floats2bfloat162_rn(v.x, v.y);
            p[1] = __floats2bfloat162_rn(v.z, v.w);
        }
        // W2 tile 32x64 fp32 -> bf16
#pragma unroll
        for (int i = 0; i < 2; i++) {
            int f = tid + i * 256;
            int r = f >> 4, s = f & 15;
            float4 v = *(const float4*)(w2 + ((size_t)(e * HDIM + ko + r)) * DDIM + dbase + s * 4);
            __nv_bfloat162* p = (__nv_bfloat162*)(W2s + r * WLD + s * 4);
            p[0] = __floats2bfloat162_rn(v.x, v.y);
            p[1] = __floats2bfloat162_rn(v.z, v.w);
        }
        __syncthreads();
#pragma unroll
        for (int ks = 0; ks < BK; ks += 16) {
            wmma::fragment<wmma::matrix_a,16,16,16,__nv_bfloat16,wmma::row_major> af;
            wmma::load_matrix_sync(af, HsA + m0 * XLD + ks, XLD);
#pragma unroll
            for (int j = 0; j < 4; j++) {
                wmma::fragment<wmma::matrix_b,16,16,16,__nv_bfloat16,wmma::row_major> bf;
                wmma::load_matrix_sync(bf, W2s + ks * WLD + j * 16, WLD);
                wmma::mma_sync(acc[j], af, bf, acc[j]);
            }
        }
        __syncthreads();
    }

#pragma unroll
    for (int j = 0; j < 4; j++)
        wmma::store_matrix_sync(Cs + m0 * SLD + j * 16, acc[j], SLD, wmma::mem_row_major);
    __syncthreads();

    // scale by routing weight, write to per-row y scratch (no atomics; rows are disjoint)
#pragma unroll
    for (int i = 0; i < 8; i++) {
        int f = tid + i * 256;
        int r = f >> 4, s = f & 15;
        if (r < valid) {
            float w = ws[r];
            float4 v = *(float4*)(Cs + r * SLD + s * 4);
            v.x *= w; v.y *= w; v.z *= w; v.w *= w;
            *(float4*)(g_y + (size_t)(off + rowBase + r) * DDIM + dbase + s * 4) = v;
        }
    }
}

// ---------------- 7) deterministic combine: out = x + y[row0] + y[row1] ----------------
__global__ __launch_bounds__(256) void k_combine(const float* __restrict__ x,
                                                 float* __restrict__ out) {
    int idx = blockIdx.x * 256 + threadIdx.x;   // over TOK * (D/4) float4s
    int t = idx >> 8;          // D/4 = 256
    int c = idx & 255;
    int r0 = g_rowOf[2*t];
    int r1 = g_rowOf[2*t+1];
    float4 xv = ((const float4*)x)[idx];
    float4 y0 = *(const float4*)(g_y + (size_t)r0 * DDIM + c * 4);
    float4 y1 = *(const float4*)(g_y + (size_t)r1 * DDIM + c * 4);
    float4 o;
    o.x = xv.x + y0.x + y1.x;
    o.y = xv.y + y0.y + y1.y;
    o.z = xv.z + y0.z + y1.z;
    o.w = xv.w + y0.w + y1.w;
    ((float4*)out)[idx] = o;
}

// ---------------- launch ----------------
extern "C" void kernel_launch(void* const* d_in, const int* in_sizes, int n_in,
                              void* d_out, int out_size) {
    const float* x  = (const float*)d_in[0];   // [2,4096,1024]
    const float* gw = (const float*)d_in[1];   // [1024,16]
    const float* w1 = (const float*)d_in[2];   // [16,1024,512]
    const float* w3 = (const float*)d_in[3];   // [16,1024,512]
    const float* w2 = (const float*)d_in[4];   // [16,512,1024]
    float* out = (float*)d_out;

    k_init<<<1, 32>>>();
    k_router<<<TOK/8, 256>>>(x, gw);
    k_scan<<<1, 32>>>();
    k_scatter<<<TOK/256, 256>>>();

    dim3 gu(HDIM/BN, TOK/BM, NEXP);   // 8 x 64 x 16
    k_up<<<gu, 256>>>(w1, w3);

    dim3 gd(DDIM/BN, TOK/BM, NEXP);   // 16 x 64 x 16
    k_down<<<gd, 256>>>(w2);

    k_combine<<<(TOK*DDIM/4)/256, 256>>>(x, out);
}

// round 4
// speedup vs baseline: 1.1269x; 1.1269x over previous
#include <cuda_runtime.h>
#include <cuda_bf16.h>
#include <mma.h>

using namespace nvcuda;

// ---------------- problem constants ----------------
#define TOK    8192
#define DDIM   1024
#define HDIM   512
#define NEXP   16
#define TOPK   2
#define ROWS_TOT (TOK*TOPK)

// ---------------- GEMM tiling ----------------
#define BM 128
#define BN 64
#define BK 32
#define XLD 40      // bf16 row stride for 32-col A tiles (80B, 16B-mult)
#define WLD 72      // bf16 row stride for 64-col B tiles (144B, 16B-mult)
#define SLD 68      // fp32 row stride for epilogue tiles
#define STAGE_UP 19456   // BM*XLD*2 + 2*BK*WLD*2
#define STAGE_DN 14848   // BM*XLD*2 + BK*WLD*2

// ---------------- device scratch (static, zero-initialized, no allocs) ----------------
__device__ alignas(256) __nv_bfloat16 g_xbf[(size_t)TOK*DDIM];                 // 16 MB
__device__ alignas(256) __nv_bfloat16 g_hb [(size_t)(ROWS_TOT+BM)*HDIM];       // ~17 MB
__device__ alignas(256) __nv_bfloat16 g_yb [(size_t)(ROWS_TOT+BM)*DDIM];       // ~34 MB
__device__ alignas(256) __nv_bfloat16 g_w1b[(size_t)NEXP*DDIM*HDIM];           // 16.8 MB
__device__ alignas(256) __nv_bfloat16 g_w3b[(size_t)NEXP*DDIM*HDIM];           // 16.8 MB
__device__ alignas(256) __nv_bfloat16 g_w2b[(size_t)NEXP*HDIM*DDIM];           // 16.8 MB
__device__ int   g_counts[NEXP];
__device__ int   g_fill[NEXP];
__device__ int   g_offsets[NEXP+1];
__device__ int   g_topk_idx[TOK*TOPK];
__device__ float g_topk_w[TOK*TOPK];
__device__ int   g_tokList[ROWS_TOT];
__device__ float g_wList[ROWS_TOT];
__device__ int   g_rowOf[TOK*TOPK];

// ---------------- cp.async helpers ----------------
__device__ __forceinline__ void cpa16(void* dst, const void* src) {
    unsigned d = (unsigned)__cvta_generic_to_shared(dst);
    asm volatile("cp.async.cg.shared.global [%0], [%1], 16;\n" :: "r"(d), "l"(src) : "memory");
}
__device__ __forceinline__ void cpa_commit() { asm volatile("cp.async.commit_group;\n" ::: "memory"); }
__device__ __forceinline__ void cpa_wait0()  { asm volatile("cp.async.wait_group 0;\n" ::: "memory"); }

// ---------------- 0) fp32 -> bf16 weight conversion (once per launch) ----------------
__global__ __launch_bounds__(256) void k_cvt(const float* __restrict__ w1,
                                             const float* __restrict__ w3,
                                             const float* __restrict__ w2) {
    const int N4 = NEXP*DDIM*HDIM/4;   // 2,097,152 float4 per array
    for (int i = blockIdx.x*256 + threadIdx.x; i < N4; i += gridDim.x*256) {
        float4 a = ((const float4*)w1)[i];
        float4 b = ((const float4*)w3)[i];
        float4 c = ((const float4*)w2)[i];
        ((__nv_bfloat162*)g_w1b)[2*i]   = __floats2bfloat162_rn(a.x, a.y);
        ((__nv_bfloat162*)g_w1b)[2*i+1] = __floats2bfloat162_rn(a.z, a.w);
        ((__nv_bfloat162*)g_w3b)[2*i]   = __floats2bfloat162_rn(b.x, b.y);
        ((__nv_bfloat162*)g_w3b)[2*i+1] = __floats2bfloat162_rn(b.z, b.w);
        ((__nv_bfloat162*)g_w2b)[2*i]   = __floats2bfloat162_rn(c.x, c.y);
        ((__nv_bfloat162*)g_w2b)[2*i+1] = __floats2bfloat162_rn(c.z, c.w);
    }
}

// ---------------- 1) zero per-expert counters ----------------
__global__ void k_init() {
    int i = threadIdx.x;
    if (i < NEXP) g_counts[i] = 0;
}

// ---------------- 2) fp32 router + bf16 cast of x ----------------
__global__ __launch_bounds__(256) void k_router(const float* __restrict__ x,
                                                const float* __restrict__ gw) {
    int lane = threadIdx.x & 31;
    int t = blockIdx.x * 8 + (threadIdx.x >> 5);
    const float* xrow = x + (size_t)t * DDIM;

    float acc[NEXP];
#pragma unroll
    for (int e = 0; e < NEXP; e++) acc[e] = 0.f;

    for (int d = lane; d < DDIM; d += 32) {
        float xv = xrow[d];
        const float4* g4 = (const float4*)(gw + (size_t)d * NEXP);
#pragma unroll
        for (int q = 0; q < 4; q++) {
            float4 v = g4[q];
            acc[q*4+0] += xv * v.x;
            acc[q*4+1] += xv * v.y;
            acc[q*4+2] += xv * v.z;
            acc[q*4+3] += xv * v.w;
        }
    }
#pragma unroll
    for (int off = 16; off; off >>= 1)
#pragma unroll
        for (int e = 0; e < NEXP; e++)
            acc[e] += __shfl_xor_sync(0xffffffffu, acc[e], off);

    if (lane == 0) {
        int e0 = 0; float l0 = acc[0];
#pragma unroll
        for (int e = 1; e < NEXP; e++) if (acc[e] > l0) { l0 = acc[e]; e0 = e; }
        int e1 = -1; float l1 = -3.4e38f;
#pragma unroll
        for (int e = 0; e < NEXP; e++) if (e != e0 && acc[e] > l1) { l1 = acc[e]; e1 = e; }
        float p1 = expf(l1 - l0);
        float w0 = 1.f / (1.f + p1);
        float w1v = p1 * w0;
        g_topk_idx[2*t]   = e0;  g_topk_idx[2*t+1] = e1;
        g_topk_w[2*t]     = w0;  g_topk_w[2*t+1]   = w1v;
        atomicAdd(&g_counts[e0], 1);
        atomicAdd(&g_counts[e1], 1);
    }

    const float4* xr4 = (const float4*)xrow;
    __nv_bfloat162* xb2 = (__nv_bfloat162*)(g_xbf + (size_t)t * DDIM);
    for (int i = lane; i < DDIM/4; i += 32) {
        float4 v = xr4[i];
        xb2[2*i]   = __floats2bfloat162_rn(v.x, v.y);
        xb2[2*i+1] = __floats2bfloat162_rn(v.z, v.w);
    }
}

// ---------------- 3) exclusive scan ----------------
__global__ void k_scan() {
    if (threadIdx.x == 0) {
        int s = 0;
        for (int e = 0; e < NEXP; e++) { g_offsets[e] = s; s += g_counts[e]; g_fill[e] = 0; }
        g_offsets[NEXP] = s;
    }
}

// ---------------- 4) scatter ----------------
__global__ void k_scatter() {
    int t = blockIdx.x * 256 + threadIdx.x;
    if (t >= TOK) return;
#pragma unroll
    for (int k = 0; k < TOPK; k++) {
        int e = g_topk_idx[2*t+k];
        int pos = atomicAdd(&g_fill[e], 1);
        int row = g_offsets[e] + pos;
        g_tokList[row] = t;
        g_wList[row]   = g_topk_w[2*t+k];
        g_rowOf[2*t+k] = row;
    }
}

// ---------------- 5) grouped up-GEMM: h = silu(X*W1) .* (X*W3), bf16, cp.async 2-stage ----------------
__global__ __launch_bounds__(256) void k_up() {
    int e = blockIdx.z;
    int n_e = g_counts[e];
    int rowBase = blockIdx.y * BM;
    if (rowBase >= n_e) return;
    int valid = min(BM, n_e - rowBase);
    int hbase = blockIdx.x * BN;
    int off = g_offsets[e];
    int tid = threadIdx.x;

    __shared__ alignas(16) unsigned char sm[2*STAGE_UP];   // 38912B; epilogue (34816B) reuses
    __shared__ int toks[BM];

    if (tid < BM)
        toks[tid] = (tid < valid) ? g_tokList[off + rowBase + tid] : g_tokList[off + rowBase];
    __syncthreads();

    auto loadStage = [&](int st, int ko) {
        unsigned char* base = sm + st * STAGE_UP;
        __nv_bfloat16* Xs  = (__nv_bfloat16*)base;
        __nv_bfloat16* W1s = Xs + BM * XLD;
        __nv_bfloat16* W3s = W1s + BK * WLD;
        // X tile: 128 rows x 32 bf16 (64B) = 512 x 16B chunks, 2/thread (gathered rows)
#pragma unroll
        for (int i = 0; i < 2; i++) {
            int c = tid + i * 256;
            int r = c >> 2, s4 = c & 3;
            cpa16(Xs + r * XLD + s4 * 8, g_xbf + (size_t)toks[r] * DDIM + ko + s4 * 8);
        }
        // W1/W3 tiles: 32 rows x 64 bf16 (128B) = 256 x 16B chunks each, 1/thread each
        {
            int r = tid >> 3, s = tid & 7;
            size_t gi = ((size_t)(e * DDIM + ko + r)) * HDIM + hbase + s * 8;
            cpa16(W1s + r * WLD + s * 8, g_w1b + gi);
            cpa16(W3s + r * WLD + s * 8, g_w3b + gi);
        }
        cpa_commit();
    };

    int wid = tid >> 5;
    int m0 = wid * 16;

    wmma::fragment<wmma::accumulator,16,16,16,float> acc1[4], acc3[4];
#pragma unroll
    for (int j = 0; j < 4; j++) { wmma::fill_fragment(acc1[j], 0.f); wmma::fill_fragment(acc3[j], 0.f); }

    loadStage(0, 0);   // prologue

    for (int k = 0; k < DDIM/BK; k++) {
        cpa_wait0();
        __syncthreads();
        if (k + 1 < DDIM/BK) loadStage((k+1) & 1, (k+1) * BK);   // prefetch overlaps compute

        unsigned char* base = sm + (k & 1) * STAGE_UP;
        const __nv_bfloat16* Xs  = (const __nv_bfloat16*)base;
        const __nv_bfloat16* W1s = Xs + BM * XLD;
        const __nv_bfloat16* W3s = W1s + BK * WLD;
#pragma unroll
        for (int ks = 0; ks < BK; ks += 16) {
            wmma::fragment<wmma::matrix_a,16,16,16,__nv_bfloat16,wmma::row_major> af;
            wmma::load_matrix_sync(af, Xs + m0 * XLD + ks, XLD);
#pragma unroll
            for (int j = 0; j < 4; j++) {
                wmma::fragment<wmma::matrix_b,16,16,16,__nv_bfloat16,wmma::row_major> bf;
                wmma::load_matrix_sync(bf, W1s + ks * WLD + j * 16, WLD);
                wmma::mma_sync(acc1[j], af, bf, acc1[j]);
                wmma::load_matrix_sync(bf, W3s + ks * WLD + j * 16, WLD);
                wmma::mma_sync(acc3[j], af, bf, acc3[j]);
            }
        }
    }
    __syncthreads();   // protect smem reuse by epilogue

    // SwiGLU in-register (acc fragments share element mapping)
#pragma unroll
    for (int j = 0; j < 4; j++)
#pragma unroll
        for (int el = 0; el < acc1[j].num_elements; el++) {
            float v1 = acc1[j].x[el];
            float sv = v1 / (1.f + __expf(-v1));
            acc1[j].x[el] = sv * acc3[j].x[el];
        }

    float* Hs = (float*)sm;
#pragma unroll
    for (int j = 0; j < 4; j++)
        wmma::store_matrix_sync(Hs + m0 * SLD + j * 16, acc1[j], SLD, wmma::mem_row_major);
    __syncthreads();

    // write h as bf16: 128x64 = 2048 float4 reads -> 8B bf16x4 writes, 8/thread
#pragma unroll
    for (int i = 0; i < 8; i++) {
        int f = tid + i * 256;
        int r = f >> 4, s = f & 15;
        if (r < valid) {
            float4 v = *(float4*)(Hs + r * SLD + s * 4);
            __nv_bfloat162* p = (__nv_bfloat162*)(g_hb + (size_t)(off + rowBase + r) * HDIM + hbase + s * 4);
            p[0] = __floats2bfloat162_rn(v.x, v.y);
            p[1] = __floats2bfloat162_rn(v.z, v.w);
        }
    }
}

// ---------------- 6) grouped down-GEMM: y = w * (h*W2), bf16, cp.async 2-stage ----------------
__global__ __launch_bounds__(256) void k_down() {
    int e = blockIdx.z;
    int n_e = g_counts[e];
    int rowBase = blockIdx.y * BM;
    if (rowBase >= n_e) return;
    int valid = min(BM, n_e - rowBase);
    int dbase = blockIdx.x * BN;
    int off = g_offsets[e];
    int tid = threadIdx.x;

    __shared__ alignas(16) unsigned char sm[BM*SLD*4];   // 34816B >= 2*STAGE_DN (29696B)
    __shared__ float ws[BM];

    if (tid < BM) ws[tid] = (tid < valid) ? g_wList[off + rowBase + tid] : 0.f;

    auto loadStage = [&](int st, int ko) {
        unsigned char* base = sm + st * STAGE_DN;
        __nv_bfloat16* As  = (__nv_bfloat16*)base;
        __nv_bfloat16* W2s = As + BM * XLD;
        // A (h) tile: rows always addressable (padded g_hb), garbage rows masked later
#pragma unroll
        for (int i = 0; i < 2; i++) {
            int c = tid + i * 256;
            int r = c >> 2, s4 = c & 3;
            cpa16(As + r * XLD + s4 * 8, g_hb + (size_t)(off + rowBase + r) * HDIM + ko + s4 * 8);
        }
        {
            int r = tid >> 3, s = tid & 7;
            cpa16(W2s + r * WLD + s * 8,
                  g_w2b + ((size_t)(e * HDIM + ko + r)) * DDIM + dbase + s * 8);
        }
        cpa_commit();
    };

    int wid = tid >> 5;
    int m0 = wid * 16;

    wmma::fragment<wmma::accumulator,16,16,16,float> acc[4];
#pragma unroll
    for (int j = 0; j < 4; j++) wmma::fill_fragment(acc[j], 0.f);

    loadStage(0, 0);

    for (int k = 0; k < HDIM/BK; k++) {
        cpa_wait0();
        __syncthreads();
        if (k + 1 < HDIM/BK) loadStage((k+1) & 1, (k+1) * BK);

        unsigned char* base = sm + (k & 1) * STAGE_DN;
        const __nv_bfloat16* As  = (const __nv_bfloat16*)base;
        const __nv_bfloat16* W2s = As + BM * XLD;
#pragma unroll
        for (int ks = 0; ks < BK; ks += 16) {
            wmma::fragment<wmma::matrix_a,16,16,16,__nv_bfloat16,wmma::row_major> af;
            wmma::load_matrix_sync(af, As + m0 * XLD + ks, XLD);
#pragma unroll
            for (int j = 0; j < 4; j++) {
                wmma::fragment<wmma::matrix_b,16,16,16,__nv_bfloat16,wmma::row_major> bf;
                wmma::load_matrix_sync(bf, W2s + ks * WLD + j * 16, WLD);
                wmma::mma_sync(acc[j], af, bf, acc[j]);
            }
        }
    }
    __syncthreads();

    float* Cs = (float*)sm;
#pragma unroll
    for (int j = 0; j < 4; j++)
        wmma::store_matrix_sync(Cs + m0 * SLD + j * 16, acc[j], SLD, wmma::mem_row_major);
    __syncthreads();

    // scale by routing weight, write bf16 y (rows disjoint, no atomics)
#pragma unroll
    for (int i = 0; i < 8; i++) {
        int f = tid + i * 256;
        int r = f >> 4, s = f & 15;
        if (r < valid) {
            float w = ws[r];
            float4 v = *(float4*)(Cs + r * SLD + s * 4);
            __nv_bfloat162* p = (__nv_bfloat162*)(g_yb + (size_t)(off + rowBase + r) * DDIM + dbase + s * 4);
            p[0] = __floats2bfloat162_rn(v.x * w, v.y * w);
            p[1] = __floats2bfloat162_rn(v.z * w, v.w * w);
        }
    }
}

// ---------------- 7) combine: out = x + y[row0] + y[row1] ----------------
__global__ __launch_bounds__(256) void k_combine(const float* __restrict__ x,
                                                 float* __restrict__ out) {
    int idx = blockIdx.x * 256 + threadIdx.x;   // over TOK * (D/4) float4s
    int t = idx >> 8;
    int c = idx & 255;
    int r0 = g_rowOf[2*t];
    int r1 = g_rowOf[2*t+1];
    float4 xv = ((const float4*)x)[idx];
    const __nv_bfloat162* p0 = (const __nv_bfloat162*)(g_yb + (size_t)r0 * DDIM + c * 4);
    const __nv_bfloat162* p1 = (const __nv_bfloat162*)(g_yb + (size_t)r1 * DDIM + c * 4);
    float2 a0 = __bfloat1622float2(p0[0]);
    float2 a1 = __bfloat1622float2(p0[1]);
    float2 b0 = __bfloat1622float2(p1[0]);
    float2 b1 = __bfloat1622float2(p1[1]);
    float4 o;
    o.x = xv.x + a0.x + b0.x;
    o.y = xv.y + a0.y + b0.y;
    o.z = xv.z + a1.x + b1.x;
    o.w = xv.w + a1.y + b1.y;
    ((float4*)out)[idx] = o;
}

// ---------------- launch ----------------
extern "C" void kernel_launch(void* const* d_in, const int* in_sizes, int n_in,
                              void* d_out, int out_size) {
    const float* x  = (const float*)d_in[0];
    const float* gw = (const float*)d_in[1];
    const float* w1 = (const float*)d_in[2];
    const float* w3 = (const float*)d_in[3];
    const float* w2 = (const float*)d_in[4];
    float* out = (float*)d_out;

    k_cvt<<<4096, 256>>>(w1, w3, w2);
    k_init<<<1, 32>>>();
    k_router<<<TOK/8, 256>>>(x, gw);
    k_scan<<<1, 32>>>();
    k_scatter<<<TOK/256, 256>>>();

    dim3 gu(HDIM/BN, TOK/BM, NEXP);   // 8 x 64 x 16
    k_up<<<gu, 256>>>();

    dim3 gd(DDIM/BN, TOK/BM, NEXP);   // 16 x 64 x 16
    k_down<<<gd, 256>>>();

    k_combine<<<(TOK*DDIM/4)/256, 256>>>(x, out);
}